// round 2
// baseline (speedup 1.0000x reference)
#include <cuda_runtime.h>
#include <math.h>

#define Nn   8192
#define Mm   2048
#define Dd   32
#define KK   64          // stacked feature depth
#define BN   128         // samples per block tile
#define BM   128         // means per block tile
#define MB   (Mm / BM)   // 16 m-blocks
#define NB   (Nn / BN)   // 64 n-blocks
#define SSTR 132         // smem row stride in floats (33 float4)
#define SMEM_BYTES ((2 * KK * SSTR + BM) * sizeof(float))

// Scratch (device globals; no allocation allowed)
__device__ __align__(16) float g_Bfeat[Mm * KK];   // [M][64]: k<32 -> mean/std, k>=32 -> -0.5/std
__device__ __align__(16) float g_c[Mm];            // -0.5 * sum_d mean^2/std
__device__ __align__(16) float g_partial[MB * Nn]; // per-mblock partial exp-sums
__device__ __align__(16) float g_dist[Nn];

// ---------------------------------------------------------------------------
// Prep: build B-features and bias c[m]. One warp per mean (D == 32 lanes).
// ---------------------------------------------------------------------------
__global__ void prep_b_kernel(const float* __restrict__ means,
                              const float* __restrict__ stds) {
    int idx = blockIdx.x * blockDim.x + threadIdx.x;  // 0 .. M*D-1
    int m = idx >> 5;
    int d = idx & 31;
    float mean = means[m * Dd + d];
    float inv  = 1.0f / stds[m * Dd + d];
    float f1 = mean * inv;
    g_Bfeat[m * KK + d]      = f1;
    g_Bfeat[m * KK + 32 + d] = -0.5f * inv;
    float cpart = -0.5f * mean * f1;
#pragma unroll
    for (int o = 16; o > 0; o >>= 1)
        cpart += __shfl_xor_sync(0xffffffffu, cpart, o);
    if (d == 0) g_c[m] = cpart;
}

// ---------------------------------------------------------------------------
// Main: 128x128 tile GEMM (K=64) + exp epilogue + in-block m-reduction.
// gridDim.x = n-block, gridDim.y = m-block. 256 threads, 8x8 per thread.
// ---------------------------------------------------------------------------
__global__ void __launch_bounds__(256, 2)
kde_main_kernel(const float* __restrict__ samples) {
    extern __shared__ float smem[];
    float* As = smem;                 // [64][SSTR]
    float* Bs = smem + KK * SSTR;     // [64][SSTR]
    float* cs = Bs + KK * SSTR;       // [128]

    const int tid = threadIdx.x;
    const int tx = tid & 15;          // m-fragment selector
    const int ty = tid >> 4;          // n-fragment selector
    const int n0 = blockIdx.x * BN;
    const int m0 = blockIdx.y * BM;

    // --- Load A tile: samples[n0..n0+127][0..31] -> As[d][n], As[d+32][n]=s^2
    {
        const float4* s4 = (const float4*)(samples + n0 * Dd);
#pragma unroll
        for (int it = 0; it < 4; it++) {
            int fid = tid + it * 256;          // 0..1023
            int n = fid >> 3;
            int d4 = (fid & 7) * 4;
            float4 v = s4[fid];
            float vv[4] = {v.x, v.y, v.z, v.w};
#pragma unroll
            for (int j = 0; j < 4; j++) {
                int d = d4 + j;
                As[d * SSTR + n] = vv[j];
                As[(d + 32) * SSTR + n] = vv[j] * vv[j];
            }
        }
    }
    // --- Load B tile: g_Bfeat[m0..m0+127][0..63] -> Bs[k][m]
    {
        const float4* b4 = (const float4*)(g_Bfeat + m0 * KK);
#pragma unroll
        for (int it = 0; it < 8; it++) {
            int fid = tid + it * 256;          // 0..2047
            int m = fid >> 4;
            int k4 = (fid & 15) * 4;
            float4 v = b4[fid];
            float vv[4] = {v.x, v.y, v.z, v.w};
#pragma unroll
            for (int j = 0; j < 4; j++)
                Bs[(k4 + j) * SSTR + m] = vv[j];
        }
    }
    if (tid < BM) cs[tid] = g_c[m0 + tid];
    __syncthreads();

    // --- Mainloop: acc[i][j] over K=64
    float acc[8][8];
#pragma unroll
    for (int i = 0; i < 8; i++)
#pragma unroll
        for (int j = 0; j < 8; j++) acc[i][j] = 0.0f;

    const float4* As4 = (const float4*)As;
    const float4* Bs4 = (const float4*)Bs;

#pragma unroll 8
    for (int k = 0; k < KK; k++) {
        int rb = k * (SSTR / 4);
        float4 a0 = As4[rb + ty];          // n = ty*4 + 0..3
        float4 a1 = As4[rb + 16 + ty];     // n = 64 + ty*4 + 0..3
        float4 b0 = Bs4[rb + tx];          // m = tx*4 + 0..3
        float4 b1 = Bs4[rb + 16 + tx];     // m = 64 + tx*4 + 0..3
        float av[8] = {a0.x, a0.y, a0.z, a0.w, a1.x, a1.y, a1.z, a1.w};
        float bv[8] = {b0.x, b0.y, b0.z, b0.w, b1.x, b1.y, b1.z, b1.w};
#pragma unroll
        for (int i = 0; i < 8; i++)
#pragma unroll
            for (int j = 0; j < 8; j++)
                acc[i][j] = fmaf(av[i], bv[j], acc[i][j]);
    }

    // --- Epilogue: logp = acc + c[m]; p = exp(logp); sum over m
    float cj[8];
#pragma unroll
    for (int j = 0; j < 8; j++) {
        int ml = (j < 4) ? (tx * 4 + j) : (64 + tx * 4 + (j - 4));
        cj[j] = cs[ml];
    }
    float nsum[8];
#pragma unroll
    for (int i = 0; i < 8; i++) {
        float s = 0.0f;
#pragma unroll
        for (int j = 0; j < 8; j++)
            s += __expf(acc[i][j] + cj[j]);
        nsum[i] = s;
    }
    // Reduce over tx (16 lanes within each half-warp)
#pragma unroll
    for (int o = 1; o < 16; o <<= 1) {
#pragma unroll
        for (int i = 0; i < 8; i++)
            nsum[i] += __shfl_xor_sync(0xffffffffu, nsum[i], o);
    }
    if (tx == 0) {
#pragma unroll
        for (int i = 0; i < 8; i++) {
            int nl = (i < 4) ? (ty * 4 + i) : (64 + ty * 4 + (i - 4));
            g_partial[blockIdx.y * Nn + n0 + nl] = nsum[i];
        }
    }
}

// ---------------------------------------------------------------------------
// dist[n] = (1/M) * sum_mb partial[mb][n]
// ---------------------------------------------------------------------------
__global__ void dist_kernel() {
    int n = blockIdx.x * blockDim.x + threadIdx.x;
    float s = 0.0f;
#pragma unroll
    for (int mb = 0; mb < MB; mb++)
        s += g_partial[mb * Nn + n];
    g_dist[n] = s * (1.0f / (float)Mm);
}

// ---------------------------------------------------------------------------
// Single block: global max/min of dist, then out[n] = (max+min) - dist[n]
// ---------------------------------------------------------------------------
__global__ void flip_kernel(float* __restrict__ out) {
    __shared__ float smx[32], smn[32];
    int tid = threadIdx.x;             // 1024 threads
    float vals[8];
    float mx = -INFINITY, mn = INFINITY;
#pragma unroll
    for (int r = 0; r < 8; r++) {
        float v = g_dist[tid + r * 1024];
        vals[r] = v;
        mx = fmaxf(mx, v);
        mn = fminf(mn, v);
    }
#pragma unroll
    for (int o = 16; o > 0; o >>= 1) {
        mx = fmaxf(mx, __shfl_xor_sync(0xffffffffu, mx, o));
        mn = fminf(mn, __shfl_xor_sync(0xffffffffu, mn, o));
    }
    if ((tid & 31) == 0) { smx[tid >> 5] = mx; smn[tid >> 5] = mn; }
    __syncthreads();
    if (tid < 32) {
        mx = smx[tid]; mn = smn[tid];
#pragma unroll
        for (int o = 16; o > 0; o >>= 1) {
            mx = fmaxf(mx, __shfl_xor_sync(0xffffffffu, mx, o));
            mn = fminf(mn, __shfl_xor_sync(0xffffffffu, mn, o));
        }
        if (tid == 0) { smx[0] = mx; smn[0] = mn; }
    }
    __syncthreads();
    float off = smx[0] + smn[0];
#pragma unroll
    for (int r = 0; r < 8; r++)
        out[tid + r * 1024] = off - vals[r];
}

// ---------------------------------------------------------------------------
extern "C" void kernel_launch(void* const* d_in, const int* in_sizes, int n_in,
                              void* d_out, int out_size) {
    const float* samples = (const float*)d_in[0];
    const float* means   = (const float*)d_in[1];
    const float* stds    = (const float*)d_in[2];
    float* out = (float*)d_out;

    cudaFuncSetAttribute(kde_main_kernel,
                         cudaFuncAttributeMaxDynamicSharedMemorySize,
                         (int)SMEM_BYTES);

    prep_b_kernel<<<(Mm * Dd) / 256, 256>>>(means, stds);
    dim3 grid(NB, MB);
    kde_main_kernel<<<grid, 256, SMEM_BYTES>>>(samples);
    dist_kernel<<<Nn / 256, 256>>>();
    flip_kernel<<<1, 1024>>>(out);
}